// round 3
// baseline (speedup 1.0000x reference)
#include <cuda_runtime.h>
#include <cstdint>
#include <cstddef>

#define VOCABP 50001
#define EMB    200
#define HID    128
#define BATCH  256
#define TLEN   500
#define NCOL   1024      // 2 dirs * 4 gates * HID
#define GDIM   512       // 4*HID per direction

// ---------------- device scratch (no allocation allowed) ----------------
__device__ float g_E[(size_t)VOCABP * NCOL];   // word -> gate_x table (bias folded)
__device__ float g_capW[4 * NCOL];             // cap  -> gate_x contribution
__device__ float g_hlast[BATCH][2 * HID];      // final concat [b][fw|bw]

// ---------------- helpers ----------------
__device__ __forceinline__ uint32_t smem_u32(const void* p)
{
    uint32_t a;
    asm("{ .reg .u64 t; cvta.to.shared.u64 t, %1; cvt.u32.u64 %0, t; }"
        : "=r"(a) : "l"(p));
    return a;
}
__device__ __forceinline__ uint32_t my_cluster_rank()
{
    uint32_t r; asm("mov.u32 %0, %%cluster_ctarank;" : "=r"(r)); return r;
}
__device__ __forceinline__ void cluster_sync()
{
    asm volatile("barrier.cluster.arrive.aligned;" ::: "memory");
    asm volatile("barrier.cluster.wait.aligned;"   ::: "memory");
}
__device__ __forceinline__ float2 dsmem_ld2(uint32_t addr, uint32_t rank)
{
    uint32_t ra; float2 v;
    asm volatile("mapa.shared::cluster.u32 %0, %1, %2;" : "=r"(ra) : "r"(addr), "r"(rank));
    asm volatile("ld.shared::cluster.v2.f32 {%0, %1}, [%2];"
                 : "=f"(v.x), "=f"(v.y) : "r"(ra));
    return v;
}

// ---------------- kernel 1: capW[c][n] = cap_emb[c] @ W[200:203] ----------------
__global__ void capw_kernel(const float* __restrict__ cap_emb,
                            const float* __restrict__ W_fw,
                            const float* __restrict__ W_bw)
{
    int idx = blockIdx.x * blockDim.x + threadIdx.x;
    if (idx >= 4 * NCOL) return;
    int c = idx >> 10, n = idx & 1023;
    const float* Wp = (n < GDIM) ? W_fw : W_bw;
    int nn = n & (GDIM - 1);
    float s = 0.f;
#pragma unroll
    for (int j = 0; j < 3; ++j)
        s += cap_emb[c * 3 + j] * Wp[(size_t)(200 + j) * GDIM + nn];
    g_capW[idx] = s;
}

// ---------------- kernel 2: E = word_emb @ [Wx_fw | Wx_bw] + bias ----------------
#define BM 64
#define BN 64
#define BK 8
__global__ void __launch_bounds__(256)
egemm_kernel(const float* __restrict__ A,      // word_emb [50001][200]
             const float* __restrict__ W_fw,   // [331][512]
             const float* __restrict__ W_bw,
             const float* __restrict__ b_fw,
             const float* __restrict__ b_bw)
{
    __shared__ float As[BK][BM];
    __shared__ float Bs[BK][BN];

    int tid = threadIdx.x;
    int n0  = blockIdx.x * BN;
    int m0  = blockIdx.y * BM;
    const float* Bp   = (n0 < GDIM) ? W_fw : W_bw;
    const float* bias = (n0 < GDIM) ? b_fw : b_bw;
    int nb = n0 & (GDIM - 1);

    int am = tid >> 2;             // 0..63
    int ak = (tid & 3) << 1;       // 0,2,4,6
    int bk = tid >> 5;             // 0..7
    int bn = (tid & 31) << 1;      // 0..62

    int  gm  = m0 + am;
    bool mok = gm < VOCABP;
    const float* Aptr = A + (size_t)(mok ? gm : 0) * EMB + ak;
    const float* Bptr = Bp + (size_t)bk * GDIM + nb + bn;

    float2 av = mok ? *(const float2*)Aptr : make_float2(0.f, 0.f);
    float2 bv = *(const float2*)Bptr;

    int tm0 = (tid >> 4) << 2;
    int tn0 = (tid & 15) << 2;
    float acc[16];
#pragma unroll
    for (int i = 0; i < 16; ++i) acc[i] = 0.f;

    for (int it = 0; it < 25; ++it) {
        As[ak][am]     = av.x;
        As[ak + 1][am] = av.y;
        *(float2*)&Bs[bk][bn] = bv;
        __syncthreads();
        if (it < 24) {
            int k0 = (it + 1) * BK;
            av = mok ? *(const float2*)(Aptr + k0) : make_float2(0.f, 0.f);
            bv = *(const float2*)(Bptr + (size_t)k0 * GDIM);
        }
#pragma unroll
        for (int kk = 0; kk < BK; ++kk) {
            float4 a4 = *(const float4*)&As[kk][tm0];
            float4 b4 = *(const float4*)&Bs[kk][tn0];
            acc[0]  += a4.x * b4.x;  acc[1]  += a4.x * b4.y;
            acc[2]  += a4.x * b4.z;  acc[3]  += a4.x * b4.w;
            acc[4]  += a4.y * b4.x;  acc[5]  += a4.y * b4.y;
            acc[6]  += a4.y * b4.z;  acc[7]  += a4.y * b4.w;
            acc[8]  += a4.z * b4.x;  acc[9]  += a4.z * b4.y;
            acc[10] += a4.z * b4.z;  acc[11] += a4.z * b4.w;
            acc[12] += a4.w * b4.x;  acc[13] += a4.w * b4.y;
            acc[14] += a4.w * b4.z;  acc[15] += a4.w * b4.w;
        }
        __syncthreads();
    }

    float bb0 = bias[nb + tn0 + 0];
    float bb1 = bias[nb + tn0 + 1];
    float bb2 = bias[nb + tn0 + 2];
    float bb3 = bias[nb + tn0 + 3];
#pragma unroll
    for (int i = 0; i < 4; ++i) {
        int gmm = m0 + tm0 + i;
        if (gmm < VOCABP) {
            float4 v;
            v.x = acc[i * 4 + 0] + bb0;
            v.y = acc[i * 4 + 1] + bb1;
            v.z = acc[i * 4 + 2] + bb2;
            v.w = acc[i * 4 + 3] + bb3;
            *(float4*)&g_E[(size_t)gmm * NCOL + n0 + tn0] = v;
        }
    }
}

// ---------------- kernel 3: cluster-pair bidirectional LSTM scan ----------------
// grid = 128 CTAs, cluster(2): cluster = (dir, batch-block of 8), rank = unit half.
// Each CTA: 64 units x 4 gates (=256 gate cols) x 8 batches, W half in smem (128KB).
// h exchange between the two ranks via DSMEM + barrier.cluster (HW, deadlock-free).
//
// smem floats: w_s[128][256] | hloc[128][8] | ebuf[2][512] | g_s[256][8]
#define W_OFF    0
#define HLOC_OFF 32768
#define EBUF_OFF 33792
#define GS_OFF   34816
#define SCAN_SMEM_F 36864
#define SCAN_SMEM   (SCAN_SMEM_F * 4)   // 147456 B

__global__ void __launch_bounds__(256) __cluster_dims__(2, 1, 1)
scan_kernel(const int* __restrict__ words, const int* __restrict__ caps,
            const float* __restrict__ W_fw, const float* __restrict__ W_bw)
{
    extern __shared__ float smem[];
    float* w_s  = smem + W_OFF;     // [k][col], col = gate*64 + ulocal
    float* hloc = smem + HLOC_OFF;  // [kglob][b], full 128-unit h for my 8 batches
    float* ebuf = smem + EBUF_OFF;  // [2][u*8+b], my 64-unit h export
    float* g_s  = smem + GS_OFF;    // [col][b]

    int tid  = threadIdx.x;
    int cid  = blockIdx.x >> 1;            // cluster id 0..63
    uint32_t r  = my_cluster_rank();       // 0/1 -> unit half
    uint32_t pr = r ^ 1u;
    int d  = cid >> 5;                     // direction
    int bb = cid & 31;                     // batch block (8 batches)
    const float* W = d ? W_bw : W_fw;      // [331][512]

    // recurrent weight half: w_s[k*256 + g*64 + u] = W[203+k][g*128 + r*64 + u]
    for (int idx = tid; idx < 128 * 256; idx += 256) {
        int k = idx >> 8, col = idx & 255;
        int g = col >> 6, u = col & 63;
        w_s[idx] = W[(size_t)(203 + k) * GDIM + (g << 7) + (r << 6) + u];
    }
    for (int idx = tid; idx < 1024; idx += 256) hloc[idx] = 0.f;
    __syncthreads();

    int cg = tid >> 3;                     // col group: 8 cols  (0..31)
    int b  = tid & 7;                      // batch lane        (0..7)
    int bglob = (bb << 3) + b;
    int c0 = cg << 3;                      // local col base
    // global E column base for my 8 cols (contiguous, same gate)
    int gcol = (d << 9) + ((cg >> 3) << 7) + ((int)r << 6) + ((cg & 7) << 3);

    int uu = tid >> 3;                     // update-phase unit base (0..31)
    float cc0 = 0.f, cc1 = 0.f;            // cell state in registers

    uint32_t ebuf_addr = smem_u32(ebuf);
    int p = 0;

    for (int step = 0; step < TLEN; ++step) {
        int t    = d ? (TLEN - 1 - step) : step;
        int widx = __ldg(&words[bglob * TLEN + t]);
        int cap  = __ldg(&caps [bglob * TLEN + t]);
        const float* erow = &g_E[(size_t)widx * NCOL + gcol];
        float4 e0  = __ldg((const float4*)erow);
        float4 e1  = __ldg((const float4*)(erow + 4));
        float4 cw0 = __ldg((const float4*)&g_capW[cap * NCOL + gcol]);
        float4 cw1 = __ldg((const float4*)&g_capW[cap * NCOL + gcol + 4]);

        // gates[b][c0..c0+7] += sum_k hloc[k][b] * w_s[k][c]
        float acc[8];
#pragma unroll
        for (int i = 0; i < 8; ++i) acc[i] = 0.f;
#pragma unroll 4
        for (int k = 0; k < 128; ++k) {
            float  hv = hloc[(k << 3) + b];
            float4 w0 = *(const float4*)&w_s[(k << 8) + c0];
            float4 w1 = *(const float4*)&w_s[(k << 8) + c0 + 4];
            acc[0] += hv * w0.x;  acc[1] += hv * w0.y;
            acc[2] += hv * w0.z;  acc[3] += hv * w0.w;
            acc[4] += hv * w1.x;  acc[5] += hv * w1.y;
            acc[6] += hv * w1.z;  acc[7] += hv * w1.w;
        }
        g_s[(c0 + 0) * 8 + b] = acc[0] + e0.x + cw0.x;
        g_s[(c0 + 1) * 8 + b] = acc[1] + e0.y + cw0.y;
        g_s[(c0 + 2) * 8 + b] = acc[2] + e0.z + cw0.z;
        g_s[(c0 + 3) * 8 + b] = acc[3] + e0.w + cw0.w;
        g_s[(c0 + 4) * 8 + b] = acc[4] + e1.x + cw1.x;
        g_s[(c0 + 5) * 8 + b] = acc[5] + e1.y + cw1.y;
        g_s[(c0 + 6) * 8 + b] = acc[6] + e1.z + cw1.z;
        g_s[(c0 + 7) * 8 + b] = acc[7] + e1.w + cw1.w;
        __syncthreads();

        // update my (u, b) cells: u = uu, uu+32. tf order i,j,f,o; forget_bias=1
#pragma unroll
        for (int it = 0; it < 2; ++it) {
            int   u  = uu + (it << 5);
            float gi = g_s[((0 * 64 + u) << 3) + b];
            float gj = g_s[((1 * 64 + u) << 3) + b];
            float gf = g_s[((2 * 64 + u) << 3) + b];
            float go = g_s[((3 * 64 + u) << 3) + b];
            float c  = (it == 0) ? cc0 : cc1;
            float si = 1.f / (1.f + __expf(-gi));
            float sf = 1.f / (1.f + __expf(-(gf + 1.f)));
            float so = 1.f / (1.f + __expf(-go));
            c = sf * c + si * tanhf(gj);
            float h = so * tanhf(c);
            if (it == 0) cc0 = c; else cc1 = c;
            int kglob = ((int)r << 6) + u;
            hloc[(kglob << 3) + b] = h;            // my half, local
            ebuf[(p << 9) + (u << 3) + b] = h;     // export to peer
            if (step == TLEN - 1)
                g_hlast[bglob][(d << 7) + kglob] = h;
        }

        cluster_sync();                            // release my ebuf / acquire peer's

        // pull peer half: hloc[pr*512 + off] = peer_ebuf[p][off]
        {
            int off = tid << 1;
            float2 v = dsmem_ld2(ebuf_addr + (((p << 9) + off) << 2), pr);
            hloc[((int)pr << 9) + off]     = v.x;
            hloc[((int)pr << 9) + off + 1] = v.y;
        }
        __syncthreads();                           // hloc complete for next step
        p ^= 1;
    }
    cluster_sync();                                // don't exit under peer DSMEM reads
}

// ---------------- kernel 4: dense head ----------------
__global__ void __launch_bounds__(64)
dense_kernel(const float* __restrict__ W1, const float* __restrict__ b1,
             const float* __restrict__ W2, const float* __restrict__ b2,
             float* __restrict__ out)
{
    __shared__ float hsh[256];
    __shared__ float dsh[64];
    int bq = blockIdx.x, j = threadIdx.x;
    for (int i = j; i < 256; i += 64) hsh[i] = g_hlast[bq][i];
    __syncthreads();
    float s = b1[j];
#pragma unroll 8
    for (int k = 0; k < 256; ++k) s += hsh[k] * W1[k * 64 + j];
    dsh[j] = (s > 0.f) ? s : (__expf(s) - 1.f);   // elu
    __syncthreads();
    if (j < 6) {
        float y = b2[j];
#pragma unroll
        for (int k = 0; k < 64; ++k) y += dsh[k] * W2[k * 6 + j];
        out[bq * 6 + j] = 1.f / (1.f + __expf(-y));
    }
}

// ---------------- launcher ----------------
extern "C" void kernel_launch(void* const* d_in, const int* in_sizes, int n_in,
                              void* d_out, int out_size)
{
    const int*   words    = (const int*)  d_in[0];
    const int*   caps     = (const int*)  d_in[1];
    const float* word_emb = (const float*)d_in[2];
    const float* cap_emb  = (const float*)d_in[3];
    const float* W_fw     = (const float*)d_in[4];
    const float* b_fw     = (const float*)d_in[5];
    const float* W_bw     = (const float*)d_in[6];
    const float* b_bw     = (const float*)d_in[7];
    const float* W1       = (const float*)d_in[8];
    const float* b1       = (const float*)d_in[9];
    const float* W2       = (const float*)d_in[10];
    const float* b2       = (const float*)d_in[11];
    float* out = (float*)d_out;

    capw_kernel<<<16, 256>>>(cap_emb, W_fw, W_bw);

    dim3 gg(NCOL / BN, (VOCABP + BM - 1) / BM);
    egemm_kernel<<<gg, 256>>>(word_emb, W_fw, W_bw, b_fw, b_bw);

    cudaFuncSetAttribute(scan_kernel, cudaFuncAttributeMaxDynamicSharedMemorySize,
                         SCAN_SMEM);
    scan_kernel<<<128, 256, SCAN_SMEM>>>(words, caps, W_fw, W_bw);

    dense_kernel<<<BATCH, 64>>>(W1, b1, W2, b2, out);
}

// round 4
// speedup vs baseline: 1.1257x; 1.1257x over previous
#include <cuda_runtime.h>
#include <cstdint>
#include <cstddef>

#define VOCABP 50001
#define EMB    200
#define HID    128
#define BATCH  256
#define TLEN   500
#define NCOL   1024      // 2 dirs * 4 gates * HID
#define GDIM   512       // 4*HID per direction

// ---------------- device scratch (no allocation allowed) ----------------
__device__ float g_E[(size_t)VOCABP * NCOL];   // word -> gate_x table (bias folded), logical layout
__device__ float g_capW[4 * NCOL];             // cap  -> gate_x contribution, logical layout
__device__ float g_hlast[BATCH][2 * HID];      // final concat [b][fw|bw]

// ---------------- helpers ----------------
__device__ __forceinline__ uint32_t smem_u32(const void* p)
{
    uint32_t a;
    asm("{ .reg .u64 t; cvta.to.shared.u64 t, %1; cvt.u32.u64 %0, t; }"
        : "=r"(a) : "l"(p));
    return a;
}
__device__ __forceinline__ uint32_t my_cluster_rank()
{
    uint32_t r; asm("mov.u32 %0, %%cluster_ctarank;" : "=r"(r)); return r;
}
__device__ __forceinline__ void cluster_arrive()
{
    asm volatile("barrier.cluster.arrive.aligned;" ::: "memory");
}
__device__ __forceinline__ void cluster_wait()
{
    asm volatile("barrier.cluster.wait.aligned;" ::: "memory");
}
__device__ __forceinline__ uint32_t mapa_u32(uint32_t addr, uint32_t rank)
{
    uint32_t ra;
    asm("mapa.shared::cluster.u32 %0, %1, %2;" : "=r"(ra) : "r"(addr), "r"(rank));
    return ra;
}
__device__ __forceinline__ float2 dsmem_ld2(uint32_t raddr)
{
    float2 v;
    asm volatile("ld.shared::cluster.v2.f32 {%0, %1}, [%2];"
                 : "=f"(v.x), "=f"(v.y) : "r"(raddr));
    return v;
}

// ---------------- kernel 1: capW[c][n] = cap_emb[c] @ W[200:203] ----------------
__global__ void capw_kernel(const float* __restrict__ cap_emb,
                            const float* __restrict__ W_fw,
                            const float* __restrict__ W_bw)
{
    int idx = blockIdx.x * blockDim.x + threadIdx.x;
    if (idx >= 4 * NCOL) return;
    int c = idx >> 10, n = idx & 1023;
    const float* Wp = (n < GDIM) ? W_fw : W_bw;
    int nn = n & (GDIM - 1);
    float s = 0.f;
#pragma unroll
    for (int j = 0; j < 3; ++j)
        s += cap_emb[c * 3 + j] * Wp[(size_t)(200 + j) * GDIM + nn];
    g_capW[idx] = s;
}

// ---------------- kernel 2: E = word_emb @ [Wx_fw | Wx_bw] + bias ----------------
// 128x128 tile, BK=8, 256 threads, 8x8 acc per thread, register-prefetch pipeline.
#define EBM 128
#define EBN 128
#define EBK 8
__global__ void __launch_bounds__(256)
egemm_kernel(const float* __restrict__ A,      // word_emb [50001][200]
             const float* __restrict__ W_fw,   // [331][512]
             const float* __restrict__ W_bw,
             const float* __restrict__ b_fw,
             const float* __restrict__ b_bw)
{
    __shared__ float As[EBK][EBM];
    __shared__ float Bs[EBK][EBN];

    int tid = threadIdx.x;
    int n0  = blockIdx.x * EBN;            // 0..896
    int m0  = blockIdx.y * EBM;
    const float* Bp   = (n0 < GDIM) ? W_fw : W_bw;
    const float* bias = (n0 < GDIM) ? b_fw : b_bw;
    int nb = n0 & (GDIM - 1);

    // loaders
    int am  = tid >> 1;                    // 0..127 (row in tile)
    int ak4 = (tid & 1) << 2;              // 0 or 4 (k offset)
    int bk  = tid >> 5;                    // 0..7
    int bn  = (tid & 31) << 2;             // 0..124

    int  gm  = m0 + am;
    bool mok = gm < VOCABP;
    const float* Ap  = A  + (size_t)(mok ? gm : 0) * EMB + ak4;
    const float* Bpp = Bp + (size_t)bk * GDIM + nb + bn;

    float4 pa = mok ? *(const float4*)Ap : make_float4(0.f, 0.f, 0.f, 0.f);
    float4 pb = *(const float4*)Bpp;

    int tm0 = (tid >> 4) << 3;             // 0..120
    int tn0 = (tid & 15) << 3;             // 0..120
    float acc[8][8];
#pragma unroll
    for (int i = 0; i < 8; ++i)
#pragma unroll
        for (int j = 0; j < 8; ++j) acc[i][j] = 0.f;

    for (int it = 0; it < 25; ++it) {
        As[ak4 + 0][am] = pa.x;
        As[ak4 + 1][am] = pa.y;
        As[ak4 + 2][am] = pa.z;
        As[ak4 + 3][am] = pa.w;
        *(float4*)&Bs[bk][bn] = pb;
        __syncthreads();
        if (it < 24) {
            int k0 = (it + 1) * EBK;
            pa = mok ? *(const float4*)(Ap + k0) : make_float4(0.f, 0.f, 0.f, 0.f);
            pb = *(const float4*)(Bpp + (size_t)k0 * GDIM);
        }
#pragma unroll
        for (int kk = 0; kk < EBK; ++kk) {
            float4 a0 = *(const float4*)&As[kk][tm0];
            float4 a1 = *(const float4*)&As[kk][tm0 + 4];
            float4 b0 = *(const float4*)&Bs[kk][tn0];
            float4 b1 = *(const float4*)&Bs[kk][tn0 + 4];
            float av[8] = {a0.x, a0.y, a0.z, a0.w, a1.x, a1.y, a1.z, a1.w};
            float bv[8] = {b0.x, b0.y, b0.z, b0.w, b1.x, b1.y, b1.z, b1.w};
#pragma unroll
            for (int i = 0; i < 8; ++i)
#pragma unroll
                for (int j = 0; j < 8; ++j) acc[i][j] += av[i] * bv[j];
        }
        __syncthreads();
    }

    float bb[8];
#pragma unroll
    for (int j = 0; j < 8; ++j) bb[j] = bias[nb + tn0 + j];
#pragma unroll
    for (int i = 0; i < 8; ++i) {
        int gmm = m0 + tm0 + i;
        if (gmm < VOCABP) {
            float4 v0, v1;
            v0.x = acc[i][0] + bb[0];  v0.y = acc[i][1] + bb[1];
            v0.z = acc[i][2] + bb[2];  v0.w = acc[i][3] + bb[3];
            v1.x = acc[i][4] + bb[4];  v1.y = acc[i][5] + bb[5];
            v1.z = acc[i][6] + bb[6];  v1.w = acc[i][7] + bb[7];
            *(float4*)&g_E[(size_t)gmm * NCOL + n0 + tn0]     = v0;
            *(float4*)&g_E[(size_t)gmm * NCOL + n0 + tn0 + 4] = v1;
        }
    }
}

// ---------------- kernel 3: cluster-pair bidirectional LSTM scan ----------------
// grid = 128 CTAs, cluster(2): cluster = (dir, batch-block of 8), rank = unit half.
// Thread (uu=tid>>3, b=tid&7) owns cols {4 gates x 2 units}: c = uu*8 + g*2 + e.
// Update runs in registers (cell state cc[2]); no gate smem roundtrip.
// Split-k pipeline: half A over my own h-half (no wait), cluster wait, pull peer
// half via DSMEM, half B, update, arrive. One HW cluster barrier per step.
//
// smem floats: w_s[128*256] | hloc[128*8] | ebuf[2*512] | capw[4*256] | wi[4000] | ci[4000]
#define W_OFF    0
#define HLOC_OFF 32768
#define EBUF_OFF 33792
#define CAPW_OFF 34816
#define WI_OFF   35840
#define CI_OFF   39840
#define SCAN_SMEM_F 43840
#define SCAN_SMEM   (SCAN_SMEM_F * 4)   // 175360 B

__device__ __forceinline__ void gate_accum(const float* __restrict__ w_s,
                                           const float* __restrict__ hloc,
                                           float (&acc)[8], int c0, int b, int k0)
{
#pragma unroll 4
    for (int k = k0; k < k0 + 64; ++k) {
        float  hv = hloc[(k << 3) + b];
        float4 w0 = *(const float4*)&w_s[(k << 8) + c0];
        float4 w1 = *(const float4*)&w_s[(k << 8) + c0 + 4];
        acc[0] += hv * w0.x;  acc[1] += hv * w0.y;
        acc[2] += hv * w0.z;  acc[3] += hv * w0.w;
        acc[4] += hv * w1.x;  acc[5] += hv * w1.y;
        acc[6] += hv * w1.z;  acc[7] += hv * w1.w;
    }
}

__global__ void __launch_bounds__(256) __cluster_dims__(2, 1, 1)
scan_kernel(const int* __restrict__ words, const int* __restrict__ caps,
            const float* __restrict__ W_fw, const float* __restrict__ W_bw)
{
    extern __shared__ float smem[];
    float* w_s    = smem + W_OFF;     // [k][c], c = uu*8 + g*2 + e (local perm)
    float* hloc   = smem + HLOC_OFF;  // [k_global][b], full 128-unit h, my 8 batches
    float* ebuf   = smem + EBUF_OFF;  // [2][ul*8+b], my 64-unit h export
    float* capw_s = smem + CAPW_OFF;  // [cap][g*64+ul]
    int*   wi     = (int*)(smem + WI_OFF);
    int*   ci     = (int*)(smem + CI_OFF);

    int tid  = threadIdx.x;
    int cid  = blockIdx.x >> 1;            // cluster id 0..63
    uint32_t r  = my_cluster_rank();       // 0/1 -> unit half
    uint32_t pr = r ^ 1u;
    int d  = cid >> 5;                     // direction
    int bb = cid & 31;                     // batch block (8 batches)
    const float* W = d ? W_bw : W_fw;      // [331][512]

    // recurrent weight half (all 128 k rows x my 256 cols, local perm order)
    for (int idx = tid; idx < 128 * 256; idx += 256) {
        int k = idx >> 8, c = idx & 255;
        int uu = c >> 3, j = c & 7, g = j >> 1, e = j & 1;
        w_s[idx] = W[(size_t)(203 + k) * GDIM + (g << 7) + ((int)r << 6) + (uu << 1) + e];
    }
    // capW slice for my (d, r) block: capw_s[cap*256 + g*64 + ul]
    for (int idx = tid; idx < 1024; idx += 256) {
        int cap = idx >> 8, rest = idx & 255, g = rest >> 6, ul = rest & 63;
        capw_s[idx] = g_capW[cap * NCOL + (d << 9) + (g << 7) + ((int)r << 6) + ul];
    }
    // word / cap index preload for my 8 batches
    for (int idx = tid; idx < TLEN * 8; idx += 256) {
        int t = idx >> 3, bl = idx & 7;
        int bg = (bb << 3) + bl;
        wi[idx] = words[bg * TLEN + t];
        ci[idx] = caps [bg * TLEN + t];
    }
    for (int idx = tid; idx < 1024; idx += 256) hloc[idx] = 0.f;
    for (int idx = tid; idx < 1024; idx += 256) ebuf[idx] = 0.f;
    __syncthreads();
    cluster_arrive();                      // publish ebuf[0]=0 to peer

    int uu = tid >> 3;                     // 0..31 (unit pair)
    int b  = tid & 7;
    int bglob = (bb << 3) + b;
    int c0 = uu << 3;
    int ebase = (d << 9) + ((int)r << 6) + (uu << 1);   // logical E col base (+ g*128)
    float cc[2] = {0.f, 0.f};

    uint32_t remote_ebuf = mapa_u32(smem_u32(ebuf), pr);
    int p = 0;

    for (int step = 0; step < TLEN; ++step) {
        int t    = d ? (TLEN - 1 - step) : step;
        int widx = wi[(t << 3) + b];
        int cap  = ci[(t << 3) + b];
        const float* erow = &g_E[(size_t)widx * NCOL + ebase];
        float2 ex[4], cw[4];
#pragma unroll
        for (int g = 0; g < 4; ++g) {
            ex[g] = __ldg((const float2*)(erow + (g << 7)));
            cw[g] = *(const float2*)&capw_s[(cap << 8) + (g << 6) + (uu << 1)];
        }

        float acc[8];
#pragma unroll
        for (int i = 0; i < 8; ++i) acc[i] = 0.f;

        // half A: my own h half (no cluster dependency)
        gate_accum(w_s, hloc, acc, c0, b, (int)r << 6);

        cluster_wait();                    // peer ebuf[p] ready
        {   // pull peer half: 2 floats per thread
            int off = tid << 1;
            float2 v = dsmem_ld2(remote_ebuf + (((p << 9) + off) << 2));
            hloc[((int)pr << 9) + off]     = v.x;
            hloc[((int)pr << 9) + off + 1] = v.y;
        }
        __syncthreads();

        // half B: peer h half
        gate_accum(w_s, hloc, acc, c0, b, (int)pr << 6);

        // register update, tf gate order i,j,f,o; forget_bias = 1
#pragma unroll
        for (int e = 0; e < 2; ++e) {
            float gi = acc[0 + e] + (e ? ex[0].y : ex[0].x) + (e ? cw[0].y : cw[0].x);
            float gj = acc[2 + e] + (e ? ex[1].y : ex[1].x) + (e ? cw[1].y : cw[1].x);
            float gf = acc[4 + e] + (e ? ex[2].y : ex[2].x) + (e ? cw[2].y : cw[2].x);
            float go = acc[6 + e] + (e ? ex[3].y : ex[3].x) + (e ? cw[3].y : cw[3].x);
            float si = 1.f / (1.f + __expf(-gi));
            float sf = 1.f / (1.f + __expf(-(gf + 1.f)));
            float so = 1.f / (1.f + __expf(-go));
            float c  = sf * cc[e] + si * tanhf(gj);
            float h  = so * tanhf(c);
            cc[e] = c;
            int ul = (uu << 1) + e;
            hloc[(((int)r << 6) + ul) * 8 + b]      = h;
            ebuf[((p ^ 1) << 9) + (ul << 3) + b]    = h;
            if (step == TLEN - 1)
                g_hlast[bglob][(d << 7) + ((int)r << 6) + ul] = h;
        }

        cluster_arrive();                  // publish ebuf[p^1]
        __syncthreads();                   // hloc my-half visible CTA-locally
        p ^= 1;
    }
    cluster_wait();                        // peer finished all pulls -> safe exit
}

// ---------------- kernel 4: dense head ----------------
// 64 blocks x 256 threads; block = 4 batches, thread = (bl, j).
__global__ void __launch_bounds__(256)
dense_kernel(const float* __restrict__ W1, const float* __restrict__ b1,
             const float* __restrict__ W2, const float* __restrict__ b2,
             float* __restrict__ out)
{
    __shared__ float hsh[4][256];
    __shared__ float dsh[4][64];
    int tid = threadIdx.x;
    int bl  = tid >> 6, j = tid & 63;
    int bq  = (blockIdx.x << 2) + bl;
    for (int i = tid; i < 1024; i += 256)
        hsh[i >> 8][i & 255] = g_hlast[(blockIdx.x << 2) + (i >> 8)][i & 255];
    __syncthreads();
    float s = b1[j];
#pragma unroll 4
    for (int k = 0; k < 256; ++k) s += hsh[bl][k] * W1[k * 64 + j];
    dsh[bl][j] = (s > 0.f) ? s : (__expf(s) - 1.f);   // elu
    __syncthreads();
    if (j < 6) {
        float y = b2[j];
#pragma unroll
        for (int k = 0; k < 64; ++k) y += dsh[bl][k] * W2[k * 6 + j];
        out[bq * 6 + j] = 1.f / (1.f + __expf(-y));
    }
}

// ---------------- launcher ----------------
extern "C" void kernel_launch(void* const* d_in, const int* in_sizes, int n_in,
                              void* d_out, int out_size)
{
    const int*   words    = (const int*)  d_in[0];
    const int*   caps     = (const int*)  d_in[1];
    const float* word_emb = (const float*)d_in[2];
    const float* cap_emb  = (const float*)d_in[3];
    const float* W_fw     = (const float*)d_in[4];
    const float* b_fw     = (const float*)d_in[5];
    const float* W_bw     = (const float*)d_in[6];
    const float* b_bw     = (const float*)d_in[7];
    const float* W1       = (const float*)d_in[8];
    const float* b1       = (const float*)d_in[9];
    const float* W2       = (const float*)d_in[10];
    const float* b2       = (const float*)d_in[11];
    float* out = (float*)d_out;

    capw_kernel<<<16, 256>>>(cap_emb, W_fw, W_bw);

    dim3 gg(NCOL / EBN, (VOCABP + EBM - 1) / EBM);
    egemm_kernel<<<gg, 256>>>(word_emb, W_fw, W_bw, b_fw, b_bw);

    cudaFuncSetAttribute(scan_kernel, cudaFuncAttributeMaxDynamicSharedMemorySize,
                         SCAN_SMEM);
    scan_kernel<<<128, 256, SCAN_SMEM>>>(words, caps, W_fw, W_bw);

    dense_kernel<<<64, 256>>>(W1, b1, W2, b2, out);
}